// round 16
// baseline (speedup 1.0000x reference)
#include <cuda_runtime.h>
#include <cuda_bf16.h>
#include <math.h>
#include <float.h>
#include <stdint.h>

#define Bb 64
#define Tt 1024
#define Cc 12
#define Dd 512
#define Ll 2
#define FFNN 2048
#define FCH 256
#define NCLS 5
#define TOPK 20
#define LNEPS 1e-5f
#define Mrows (Bb*Tt)

// ------------------------- scratch (device globals; no allocs allowed) ----
__device__ float g_h [Bb*Tt*Dd];
__device__ float g_a [Bb*Tt*Dd];
__device__ float g_b [Bb*Tt*Dd];
__device__ float g_c [Bb*Tt*Dd];
__device__ float g_qt[Bb*Tt*Dd];
__device__ float g_kt[Bb*Tt*Dd];
__device__ float g_ffn[(size_t)Bb*Tt*FFNN];   // fc1 bf16 hi/lo
__device__ float g_part[Bb*64*1026];          // fft partials; also meanT partials
__device__ float g_sf[Bb*1026];
__device__ int   g_delay[Bb*TOPK];
__device__ float g_wt[Bb*TOPK];
__device__ float g_scale[Bb*Cc];
__device__ float g_pos[Tt*Dd];
__device__ float g_bqk[Ll][1024];
__device__ float g_bvo[Ll][Dd];
// bf16 split buffers (activations) and weights
__device__ __nv_bfloat16 g_ah[(size_t)Mrows*Dd];
__device__ __nv_bfloat16 g_al[(size_t)Mrows*Dd];
__device__ __nv_bfloat16 g_wh[8*1024*1024];
__device__ __nv_bfloat16 g_wl[8*1024*1024];

// ------------------------- helpers ---------------------------------------
__device__ __forceinline__ uint32_t smem_u32(const void* p) {
    uint32_t a;
    asm("{ .reg .u64 t; cvta.to.shared.u64 t, %1; cvt.u32.u64 %0, t; }" : "=r"(a) : "l"(p));
    return a;
}
__device__ __forceinline__ void cpasync16(uint32_t sa, const void* ga) {
    asm volatile("cp.async.cg.shared.global [%0], [%1], 16;\n"
        :: "r"(sa), "l"(__cvta_generic_to_global(ga)));
}
#define CP_COMMIT() asm volatile("cp.async.commit_group;\n" ::: "memory")
#define CP_WAIT(n)  asm volatile("cp.async.wait_group %0;\n" :: "n"(n) : "memory")

__device__ __forceinline__ void mma16816(float (&d)[4], const uint32_t (&a)[4], const uint32_t (&b)[2]) {
    asm volatile("mma.sync.aligned.m16n8k16.row.col.f32.bf16.bf16.f32 "
        "{%0,%1,%2,%3}, {%4,%5,%6,%7}, {%8,%9}, {%0,%1,%2,%3};\n"
        : "+f"(d[0]), "+f"(d[1]), "+f"(d[2]), "+f"(d[3])
        : "r"(a[0]), "r"(a[1]), "r"(a[2]), "r"(a[3]), "r"(b[0]), "r"(b[1]));
}
__device__ __forceinline__ void lds_a(uint32_t (&a)[4][4], uint32_t base, int wm0, int lane, int h) {
    uint32_t addr = base + (uint32_t)((wm0 + (lane & 15)) * 80 + ((h << 1) + (lane >> 4)) * 16);
    #pragma unroll
    for (int i = 0; i < 4; i++) {
        asm volatile("ldmatrix.sync.aligned.m8n8.x4.shared.b16 {%0,%1,%2,%3}, [%4];\n"
            : "=r"(a[i][0]), "=r"(a[i][1]), "=r"(a[i][2]), "=r"(a[i][3])
            : "r"(addr + i * 16 * 80));
    }
}
__device__ __forceinline__ void lds_b(uint32_t (&b)[4][2], uint32_t base, int wn0, int lane, int h) {
    uint32_t addr = base + (uint32_t)((wn0 + (lane & 7)) * 80 + ((h << 1) + ((lane >> 3) & 1)) * 16);
    #pragma unroll
    for (int j = 0; j < 4; j++) {
        asm volatile("ldmatrix.sync.aligned.m8n8.x2.shared.b16 {%0,%1}, [%2];\n"
            : "=r"(b[j][0]), "=r"(b[j][1]) : "r"(addr + j * 8 * 80));
    }
}
// fp32 float4 -> bf16 hi/lo split store into g_ah/g_al at element offset eo
__device__ __forceinline__ void store_split4(float4 o, size_t eo) {
    __nv_bfloat16 h0 = __float2bfloat16_rn(o.x), h1 = __float2bfloat16_rn(o.y);
    __nv_bfloat16 h2 = __float2bfloat16_rn(o.z), h3 = __float2bfloat16_rn(o.w);
    __nv_bfloat16 l0 = __float2bfloat16_rn(o.x - __bfloat162float(h0));
    __nv_bfloat16 l1 = __float2bfloat16_rn(o.y - __bfloat162float(h1));
    __nv_bfloat16 l2 = __float2bfloat16_rn(o.z - __bfloat162float(h2));
    __nv_bfloat16 l3 = __float2bfloat16_rn(o.w - __bfloat162float(h3));
    *(__nv_bfloat162*)(g_ah + eo)     = __nv_bfloat162(h0, h1);
    *(__nv_bfloat162*)(g_ah + eo + 2) = __nv_bfloat162(h2, h3);
    *(__nv_bfloat162*)(g_al + eo)     = __nv_bfloat162(l0, l1);
    *(__nv_bfloat162*)(g_al + eo + 2) = __nv_bfloat162(l2, l3);
}

// ------------------------- merged pos + scale ------------------------------
__global__ void posscale_kernel(const float* __restrict__ x) {
    if (blockIdx.x < 2048) {
        int idx = blockIdx.x * 256 + threadIdx.x;
        int t = idx / Dd, d = idx % Dd;
        int j = (d < 256) ? d : d - 256;
        double freq = exp(-(double)j * (log(10000.0) / 256.0));
        double arg = (double)t * freq;
        g_pos[idx] = (float)((d < 256) ? sin(arg) : cos(arg));
    } else {
        int pair = (blockIdx.x - 2048) * 8 + (threadIdx.x >> 5);
        int lane = threadIdx.x & 31;
        int b = pair / Cc, c = pair % Cc;
        float s = 0.f;
        for (int t = lane; t < Tt; t += 32)
            s += fabsf(x[(b * Tt + t) * Cc + c]);
        for (int o = 16; o; o >>= 1) s += __shfl_down_sync(0xffffffffu, s, o);
        if (lane == 0) g_scale[b * Cc + c] = fmaxf(s / Tt, 1e-10f);
    }
}

// ------------------------- consolidated weight prep -----------------------
#define LW       2883584
#define OFF_QK   0
#define OFF_WVO  524288
#define OFF_FC1  786432
#define OFF_FC2  1835008
__global__ void prep_kernel(const float* __restrict__ attn_w, const float* __restrict__ attn_b,
                            const float* __restrict__ fc1w, const float* __restrict__ fc2w,
                            __nv_bfloat16* __restrict__ WHp, __nv_bfloat16* __restrict__ WLp) {
    __shared__ float tile[32][33];
    int bid = blockIdx.x;
    int l = bid / 2817, r = bid % 2817;
    size_t lb = (size_t)l * LW;
    int tx = threadIdx.x, ty = threadIdx.y;
    int tid = ty * 32 + tx;
    const float* Wv = attn_w + (size_t)(l * 4 + 2) * Dd * Dd;
    const float* Wo = attn_w + (size_t)(l * 4 + 3) * Dd * Dd;

    if (r == 2816) {  // bias prep
        const float* bq = attn_b + (size_t)(l * 4 + 0) * Dd;
        const float* bk = attn_b + (size_t)(l * 4 + 1) * Dd;
        const float* bv = attn_b + (size_t)(l * 4 + 2) * Dd;
        const float* bo = attn_b + (size_t)(l * 4 + 3) * Dd;
        #pragma unroll
        for (int q = 0; q < 2; q++) {
            int n = tid + q * 256;
            float s = 0.f;
            for (int k = 0; k < Dd; k++) s += bv[k] * Wo[k * Dd + n];
            g_bvo[l][n] = s + bo[n];
            g_bqk[l][n] = bq[n];
            g_bqk[l][n + Dd] = bk[n];
        }
        return;
    }

    const float* src = nullptr; __nv_bfloat16 *oh, *ol;
    int K, N, t;
    bool compute_wvo = false;
    if (r < 256) {
        src = attn_w + (size_t)(l * 4 + 0) * Dd * Dd; oh = WHp + lb + OFF_QK; ol = WLp + lb + OFF_QK;
        K = Dd; N = Dd; t = r;
    } else if (r < 512) {
        src = attn_w + (size_t)(l * 4 + 1) * Dd * Dd; oh = WHp + lb + OFF_QK + Dd * Dd; ol = WLp + lb + OFF_QK + Dd * Dd;
        K = Dd; N = Dd; t = r - 256;
    } else if (r < 768) {
        oh = WHp + lb + OFF_WVO; ol = WLp + lb + OFF_WVO;
        K = Dd; N = Dd; t = r - 512; compute_wvo = true;
    } else if (r < 1792) {
        src = fc1w + (size_t)l * Dd * FFNN; oh = WHp + lb + OFF_FC1; ol = WLp + lb + OFF_FC1;
        K = Dd; N = FFNN; t = r - 768;
    } else {
        src = fc2w + (size_t)l * FFNN * Dd; oh = WHp + lb + OFF_FC2; ol = WLp + lb + OFF_FC2;
        K = FFNN; N = Dd; t = r - 1792;
    }
    int nt = N / 32;
    int n0 = (t % nt) * 32, k0 = (t / nt) * 32;

    if (compute_wvo) {
        float s[4] = {0.f, 0.f, 0.f, 0.f};
        for (int k = 0; k < Dd; k++) {
            float wo = Wo[k * Dd + n0 + tx];
            #pragma unroll
            for (int q = 0; q < 4; q++)
                s[q] += Wv[(size_t)(k0 + ty + 8 * q) * Dd + k] * wo;
        }
        #pragma unroll
        for (int q = 0; q < 4; q++) tile[ty + 8 * q][tx] = s[q];
    } else {
        for (int i = ty; i < 32; i += 8)
            tile[i][tx] = src[(size_t)(k0 + i) * N + n0 + tx];
    }
    __syncthreads();
    for (int i = ty; i < 32; i += 8) {
        float v = tile[tx][i];
        __nv_bfloat16 h = __float2bfloat16_rn(v);
        size_t o = (size_t)(n0 + i) * K + k0 + tx;
        oh[o] = h;
        ol[o] = __float2bfloat16_rn(v - __bfloat162float(h));
    }
}

// ------------------------- bf16 mma.sync GEMM (2/3-pass split) ------------
#define TILEB 10240            // 128 rows * 80 bytes
#define STAGEB (4*TILEB)       // Ah, Al, Bh, Bl
#define GSMEM  (2*STAGEB)      // 81920
template<int ACT, int RES, int OUTBF, int PASSES>
__global__ __launch_bounds__(256, 2) void gemm_bf16(
        const __nv_bfloat16* __restrict__ Ah, const __nv_bfloat16* __restrict__ Al,
        const __nv_bfloat16* __restrict__ Bh, const __nv_bfloat16* __restrict__ Bl,
        const float* __restrict__ bias, const float* __restrict__ res,
        float* __restrict__ C, __nv_bfloat16* __restrict__ Ch, __nv_bfloat16* __restrict__ Cl,
        int M, int N, int K) {
    extern __shared__ char smem[];
    uint32_t sb = smem_u32(smem);
    int tid = threadIdx.x, lane = tid & 31, wid = tid >> 5;
    int m0 = blockIdx.y * 128, n0 = blockIdx.x * 128;
    int wm0 = (wid & 1) * 64, wn0 = (wid >> 1) * 32;

    float acc[4][4][4];
    #pragma unroll
    for (int i = 0; i < 4; i++)
        #pragma unroll
        for (int j = 0; j < 4; j++)
            #pragma unroll
            for (int r = 0; r < 4; r++) acc[i][j][r] = 0.f;

    const __nv_bfloat16* g0 = Ah + (size_t)m0 * K;
    const __nv_bfloat16* g1 = Al + (size_t)m0 * K;
    const __nv_bfloat16* g2 = Bh + (size_t)n0 * K;
    const __nv_bfloat16* g3 = Bl + (size_t)n0 * K;
    int lrow = tid >> 2;
    int lchB = (tid & 3) * 16;
    int lchE = (tid & 3) * 8;

    int NC = K >> 5;
    {
        uint32_t sb0 = sb + lrow * 80 + lchB;
        size_t go = (size_t)lrow * K + lchE;
        size_t go2 = go + (size_t)64 * K;
        cpasync16(sb0,                       g0 + go);
        cpasync16(sb0 + 64*80,               g0 + go2);
        cpasync16(sb0 + TILEB,               g1 + go);
        cpasync16(sb0 + TILEB + 64*80,       g1 + go2);
        cpasync16(sb0 + 2*TILEB,             g2 + go);
        cpasync16(sb0 + 2*TILEB + 64*80,     g2 + go2);
        if (PASSES == 3) {
            cpasync16(sb0 + 3*TILEB,         g3 + go);
            cpasync16(sb0 + 3*TILEB + 64*80, g3 + go2);
        }
        CP_COMMIT();
    }
    for (int c = 0; c < NC; c++) {
        if (c + 1 < NC) {
            uint32_t sb1 = sb + ((c + 1) & 1) * STAGEB + lrow * 80 + lchB;
            size_t go = (size_t)lrow * K + (size_t)(c + 1) * 32 + lchE;
            size_t go2 = go + (size_t)64 * K;
            cpasync16(sb1,                   g0 + go);
            cpasync16(sb1 + 64*80,           g0 + go2);
            cpasync16(sb1 + TILEB,           g1 + go);
            cpasync16(sb1 + TILEB + 64*80,   g1 + go2);
            cpasync16(sb1 + 2*TILEB,         g2 + go);
            cpasync16(sb1 + 2*TILEB + 64*80, g2 + go2);
            if (PASSES == 3) {
                cpasync16(sb1 + 3*TILEB,         g3 + go);
                cpasync16(sb1 + 3*TILEB + 64*80, g3 + go2);
            }
            CP_COMMIT();
            CP_WAIT(1);
        } else {
            CP_WAIT(0);
        }
        __syncthreads();
        uint32_t Ahb = sb + (c & 1) * STAGEB;
        uint32_t Alb = Ahb + TILEB, Bhb = Ahb + 2*TILEB, Blb = Ahb + 3*TILEB;
        #pragma unroll
        for (int h = 0; h < 2; h++) {
            uint32_t af[4][4], bfh[4][2], bfl[4][2];
            lds_a(af, Ahb, wm0, lane, h);
            lds_b(bfh, Bhb, wn0, lane, h);
            #pragma unroll
            for (int i = 0; i < 4; i++)
                #pragma unroll
                for (int j = 0; j < 4; j++) mma16816(acc[i][j], af[i], bfh[j]);
            if (PASSES == 3) {
                lds_b(bfl, Blb, wn0, lane, h);
                #pragma unroll
                for (int i = 0; i < 4; i++)
                    #pragma unroll
                    for (int j = 0; j < 4; j++) mma16816(acc[i][j], af[i], bfl[j]);
            }
            lds_a(af, Alb, wm0, lane, h);
            #pragma unroll
            for (int i = 0; i < 4; i++)
                #pragma unroll
                for (int j = 0; j < 4; j++) mma16816(acc[i][j], af[i], bfh[j]);
        }
        __syncthreads();
    }

    int rb = m0 + wm0 + (lane >> 2);
    int cb = n0 + wn0 + (lane & 3) * 2;
    #pragma unroll
    for (int i = 0; i < 4; i++) {
        #pragma unroll
        for (int j = 0; j < 4; j++) {
            #pragma unroll
            for (int half = 0; half < 2; half++) {
                int r = rb + i * 16 + half * 8;
                int col = cb + j * 8;
                float v0 = acc[i][j][half * 2 + 0] + bias[col];
                float v1 = acc[i][j][half * 2 + 1] + bias[col + 1];
                if (ACT == 1) {
                    v0 = 0.5f * v0 * (1.f + erff(v0 * 0.70710678118654752f));
                    v1 = 0.5f * v1 * (1.f + erff(v1 * 0.70710678118654752f));
                }
                if (RES) {
                    const float2 rr = *(const float2*)&res[(size_t)r * N + col];
                    v0 += rr.x; v1 += rr.y;
                }
                if (OUTBF) {
                    __nv_bfloat16 h0 = __float2bfloat16_rn(v0), h1 = __float2bfloat16_rn(v1);
                    __nv_bfloat16 l0 = __float2bfloat16_rn(v0 - __bfloat162float(h0));
                    __nv_bfloat16 l1 = __float2bfloat16_rn(v1 - __bfloat162float(h1));
                    *(__nv_bfloat162*)&Ch[(size_t)r * N + col] = __nv_bfloat162(h0, h1);
                    *(__nv_bfloat162*)&Cl[(size_t)r * N + col] = __nv_bfloat162(l0, l1);
                } else {
                    *(float2*)&C[(size_t)r * N + col] = make_float2(v0, v1);
                }
            }
        }
    }
}

// ------------------------- QK GEMM: 3-split, transposed (B,D,T) output ----
#define QK_SMEM  (128*129*4 > GSMEM ? 128*129*4 : GSMEM)
__global__ __launch_bounds__(256, 2) void gemm_qk(
        const __nv_bfloat16* __restrict__ Ah, const __nv_bfloat16* __restrict__ Al,
        const __nv_bfloat16* __restrict__ Bh, const __nv_bfloat16* __restrict__ Bl,
        const float* __restrict__ bias, float* __restrict__ Qo, float* __restrict__ Ko) {
    const int K = Dd;
    extern __shared__ char smem[];
    uint32_t sb = smem_u32(smem);
    int tid = threadIdx.x, lane = tid & 31, wid = tid >> 5;
    int m0 = blockIdx.y * 128, n0 = blockIdx.x * 128;
    int wm0 = (wid & 1) * 64, wn0 = (wid >> 1) * 32;

    float acc[4][4][4];
    #pragma unroll
    for (int i = 0; i < 4; i++)
        #pragma unroll
        for (int j = 0; j < 4; j++)
            #pragma unroll
            for (int r = 0; r < 4; r++) acc[i][j][r] = 0.f;

    const __nv_bfloat16* g0 = Ah + (size_t)m0 * K;
    const __nv_bfloat16* g1 = Al + (size_t)m0 * K;
    const __nv_bfloat16* g2 = Bh + (size_t)n0 * K;
    const __nv_bfloat16* g3 = Bl + (size_t)n0 * K;
    int lrow = tid >> 2;
    int lchB = (tid & 3) * 16;
    int lchE = (tid & 3) * 8;

    const int NC = K >> 5;
    {
        uint32_t sb0 = sb + lrow * 80 + lchB;
        size_t go = (size_t)lrow * K + lchE;
        size_t go2 = go + (size_t)64 * K;
        cpasync16(sb0,                       g0 + go);
        cpasync16(sb0 + 64*80,               g0 + go2);
        cpasync16(sb0 + TILEB,               g1 + go);
        cpasync16(sb0 + TILEB + 64*80,       g1 + go2);
        cpasync16(sb0 + 2*TILEB,             g2 + go);
        cpasync16(sb0 + 2*TILEB + 64*80,     g2 + go2);
        cpasync16(sb0 + 3*TILEB,             g3 + go);
        cpasync16(sb0 + 3*TILEB + 64*80,     g3 + go2);
        CP_COMMIT();
    }
    for (int c = 0; c < NC; c++) {
        if (c + 1 < NC) {
            uint32_t sb1 = sb + ((c + 1) & 1) * STAGEB + lrow * 80 + lchB;
            size_t go = (size_t)lrow * K + (size_t)(c + 1) * 32 + lchE;
            size_t go2 = go + (size_t)64 * K;
            cpasync16(sb1,                   g0 + go);
            cpasync16(sb1 + 64*80,           g0 + go2);
            cpasync16(sb1 + TILEB,           g1 + go);
            cpasync16(sb1 + TILEB + 64*80,   g1 + go2);
            cpasync16(sb1 + 2*TILEB,         g2 + go);
            cpasync16(sb1 + 2*TILEB + 64*80, g2 + go2);
            cpasync16(sb1 + 3*TILEB,         g3 + go);
            cpasync16(sb1 + 3*TILEB + 64*80, g3 + go2);
            CP_COMMIT();
            CP_WAIT(1);
        } else {
            CP_WAIT(0);
        }
        __syncthreads();
        uint32_t Ahb = sb + (c & 1) * STAGEB;
        uint32_t Alb = Ahb + TILEB, Bhb = Ahb + 2*TILEB, Blb = Ahb + 3*TILEB;
        #pragma unroll
        for (int h = 0; h < 2; h++) {
            uint32_t af[4][4], bfh[4][2], bfl[4][2];
            lds_a(af, Ahb, wm0, lane, h);
            lds_b(bfh, Bhb, wn0, lane, h);
            #pragma unroll
            for (int i = 0; i < 4; i++)
                #pragma unroll
                for (int j = 0; j < 4; j++) mma16816(acc[i][j], af[i], bfh[j]);
            lds_b(bfl, Blb, wn0, lane, h);
            #pragma unroll
            for (int i = 0; i < 4; i++)
                #pragma unroll
                for (int j = 0; j < 4; j++) mma16816(acc[i][j], af[i], bfl[j]);
            lds_a(af, Alb, wm0, lane, h);
            #pragma unroll
            for (int i = 0; i < 4; i++)
                #pragma unroll
                for (int j = 0; j < 4; j++) mma16816(acc[i][j], af[i], bfh[j]);
        }
        __syncthreads();
    }

    // epilogue: bias add -> smem staging (pitch 129) -> transposed store
    float* s = (float*)smem;
    int srow = wm0 + (lane >> 2);
    int scol = wn0 + (lane & 3) * 2;
    #pragma unroll
    for (int i = 0; i < 4; i++) {
        #pragma unroll
        for (int j = 0; j < 4; j++) {
            #pragma unroll
            for (int half = 0; half < 2; half++) {
                int rr = srow + i * 16 + half * 8;
                int cc = scol + j * 8;
                s[rr * 129 + cc]     = acc[i][j][half * 2 + 0] + bias[n0 + cc];
                s[rr * 129 + cc + 1] = acc[i][j][half * 2 + 1] + bias[n0 + cc + 1];
            }
        }
    }
    __syncthreads();
    int b = m0 >> 10, t0 = m0 & 1023;
    int dl = tid >> 1, th = tid & 1;
    int dg = n0 + dl;
    float* dst = (dg < Dd ? Qo + (size_t)(b * Dd + dg) * Tt
                          : Ko + (size_t)(b * Dd + dg - Dd) * Tt) + t0 + th * 64;
    #pragma unroll
    for (int u = 0; u < 64; u += 4) {
        float4 v;
        v.x = s[(th * 64 + u + 0) * 129 + dl];
        v.y = s[(th * 64 + u + 1) * 129 + dl];
        v.z = s[(th * 64 + u + 2) * 129 + dl];
        v.w = s[(th * 64 + u + 3) * 129 + dl];
        *(float4*)(dst + u) = v;
    }
}

// ------------------------- small helpers ---------------------------------
__device__ __forceinline__ float blockReduceSum128(float v, float* sh) {
    sh[threadIdx.x] = v; __syncthreads();
    for (int o = 64; o; o >>= 1) {
        if (threadIdx.x < o) sh[threadIdx.x] += sh[threadIdx.x + o];
        __syncthreads();
    }
    float r = sh[0]; __syncthreads();
    return r;
}

// ------------------------- embedding + pos + LN + split (fused) -----------
__global__ void embed_kernel(const float* __restrict__ x, const float* __restrict__ w,
                             const float* __restrict__ gamma, const float* __restrict__ beta) {
    int bt = blockIdx.x;
    int b = bt >> 10, t = bt & 1023;
    __shared__ float xs[Cc], ls[Cc];
    __shared__ float sh[128];
    if (threadIdx.x < Cc) {
        float sc = g_scale[b * Cc + threadIdx.x];
        xs[threadIdx.x] = x[bt * Cc + threadIdx.x] / sc;
        ls[threadIdx.x] = logf(sc);
    }
    __syncthreads();
    int d0 = threadIdx.x * 4;
    float4 v = *(const float4*)&g_pos[t * Dd + d0];
    #pragma unroll
    for (int c = 0; c < Cc; c++) {
        float xc = xs[c], lc = ls[c];
        float4 w1 = *(const float4*)&w[c * Dd + d0];
        float4 w2 = *(const float4*)&w[(24 + c) * Dd + d0];
        v.x += xc * w1.x + lc * w2.x;
        v.y += xc * w1.y + lc * w2.y;
        v.z += xc * w1.z + lc * w2.z;
        v.w += xc * w1.w + lc * w2.w;
    }
    float s = v.x + v.y + v.z + v.w;
    s = blockReduceSum128(s, sh);
    float mu = s / Dd;
    float dx = v.x - mu, dy = v.y - mu, dz = v.z - mu, dw = v.w - mu;
    float sq = dx * dx + dy * dy + dz * dz + dw * dw;
    sq = blockReduceSum128(sq, sh);
    float rstd = rsqrtf(sq / Dd + LNEPS);
    float4 gg = *(const float4*)&gamma[d0];
    float4 bbv = *(const float4*)&beta[d0];
    float4 o;
    o.x = dx * rstd * gg.x + bbv.x;
    o.y = dy * rstd * gg.y + bbv.y;
    o.z = dz * rstd * gg.z + bbv.z;
    o.w = dw * rstd * gg.w + bbv.w;
    *(float4*)&g_h[(size_t)bt * Dd + d0] = o;
    store_split4(o, (size_t)bt * Dd + d0);
}

// ------------------------- fused LayerNorm + series decomp + split --------
template<int MEAN>
__global__ __launch_bounds__(128) void ln_decomp_kernel(
        const float* __restrict__ in, const float* __restrict__ gamma,
        const float* __restrict__ beta, float* __restrict__ out) {
    int b = blockIdx.x;
    int t0 = blockIdx.y * 64;
    int tid = threadIdx.x, lane = tid & 31, w = tid >> 5;
    __shared__ float smu[89], srs[89];
    const float* ib = in + (size_t)b * Tt * Dd;

    for (int j = w; j < 89; j += 4) {
        int row = t0 - 12 + j; row = row < 0 ? 0 : (row > Tt - 1 ? Tt - 1 : row);
        const float4* rp = (const float4*)(ib + (size_t)row * Dd);
        float s = 0.f, q = 0.f;
        for (int c = lane; c < 128; c += 32) {
            float4 v = rp[c];
            s += v.x + v.y + v.z + v.w;
            q += v.x * v.x + v.y * v.y + v.z * v.z + v.w * v.w;
        }
        for (int o = 16; o; o >>= 1) {
            s += __shfl_down_sync(0xffffffffu, s, o);
            q += __shfl_down_sync(0xffffffffu, q, o);
        }
        if (lane == 0) {
            float mu = s / Dd;
            smu[j] = mu;
            srs[j] = rsqrtf(q / Dd - mu * mu + LNEPS);
        }
    }
    __syncthreads();

    int d0 = tid * 4;
    float4 gg = *(const float4*)&gamma[d0];
    float4 bv = *(const float4*)&beta[d0];
    #define LDN(J, R) { int row = t0 - 12 + (J); row = row < 0 ? 0 : (row > Tt - 1 ? Tt - 1 : row); \
        float4 v = *(const float4*)(ib + (size_t)row * Dd + d0); \
        float mu = smu[J], rs = srs[J]; \
        (R).x = (v.x - mu) * rs * gg.x + bv.x; (R).y = (v.y - mu) * rs * gg.y + bv.y; \
        (R).z = (v.z - mu) * rs * gg.z + bv.z; (R).w = (v.w - mu) * rs * gg.w + bv.w; }
    float4 s = make_float4(0.f, 0.f, 0.f, 0.f);
    for (int j = 0; j < 25; j++) {
        float4 r; LDN(j, r);
        s.x += r.x; s.y += r.y; s.z += r.z; s.w += r.w;
    }
    const float inv = 1.f / 25.f;
    float4 msum = make_float4(0.f, 0.f, 0.f, 0.f);
    for (int t = 0; t < 64; t++) {
        int j = 12 + t;
        float4 xv; LDN(j, xv);
        float4 o;
        o.x = xv.x - s.x * inv; o.y = xv.y - s.y * inv;
        o.z = xv.z - s.z * inv; o.w = xv.w - s.w * inv;
        size_t eo = (size_t)(b * Tt + t0 + t) * Dd + d0;
        *(float4*)&out[eo] = o;
        store_split4(o, eo);
        if (MEAN) {
            msum.x += o.x; msum.y += o.y; msum.z += o.z; msum.w += o.w;
        }
        if (t < 63) {
            float4 ra, rr;
            LDN(j + 13, ra);
            LDN(j - 12, rr);
            s.x += ra.x - rr.x; s.y += ra.y - rr.y;
            s.z += ra.z - rr.z; s.w += ra.w - rr.w;
        }
    }
    #undef LDN
    if (MEAN)
        *(float4*)&g_part[(size_t)(b * 16 + blockIdx.y) * Dd + d0] = msum;
}

// ------------------------- 1024-pt FFT core (thread-count parametric) -----
__device__ __forceinline__ void fft1024_inplace(float2* z, const float2* tw, int tid, int nthr) {
    #pragma unroll
    for (int s = 1; s <= 10; s++) {
        int half = 1 << (s - 1);
        for (int bf = tid; bf < 512; bf += nthr) {
            int pos = bf & (half - 1);
            int i1 = ((bf >> (s - 1)) << s) + pos;
            float2 w = tw[pos << (10 - s)];
            float2 u = z[i1], v = z[i1 + half];
            float trr = w.x * v.x - w.y * v.y;
            float tii = w.x * v.y + w.y * v.x;
            z[i1]        = make_float2(u.x + trr, u.y + tii);
            z[i1 + half] = make_float2(u.x - trr, u.y - tii);
        }
        __syncthreads();
    }
}

__device__ __forceinline__ void fill_twiddle(float2* tw, int tid, int nthr) {
    for (int j = tid; j < 512; j += nthr) {
        float sn, cs;
        sincosf(-6.283185307179586477f * (float)j / 1024.f, &sn, &cs);
        tw[j] = make_float2(cs, sn);
    }
}

// q,k packed FFT -> cross-spectrum partials; 8 channels per block; 256 thr
__global__ __launch_bounds__(256) void fft_corr_kernel() {
    int bx = blockIdx.x;
    int b = bx >> 6, grp = bx & 63;
    __shared__ float2 z[1024];
    __shared__ float2 tw[512];
    int tid = threadIdx.x;
    fill_twiddle(tw, tid, 256);
    float sr[3], si[3];
    #pragma unroll
    for (int q = 0; q < 3; q++) { sr[q] = 0.f; si[q] = 0.f; }
    const float* qbase = g_qt + (size_t)(b * Dd + grp * 8) * Tt;
    const float* kbase = g_kt + (size_t)(b * Dd + grp * 8) * Tt;
    for (int ch = 0; ch < 8; ch++) {
        __syncthreads();
        for (int i = tid; i < 1024; i += 256) {
            int r = __brev((unsigned)i) >> 22;
            z[r] = make_float2(qbase[ch * Tt + i], kbase[ch * Tt + i]);
        }
        __syncthreads();
        fft1024_inplace(z, tw, tid, 256);
        #pragma unroll
        for (int q = 0; q < 3; q++) {
            int f = tid + q * 256;
            if (f <= 512) {
                float2 Zf = z[f];
                float2 Zn = z[(1024 - f) & 1023];
                float Qr = 0.5f * (Zf.x + Zn.x), Qi = 0.5f * (Zf.y - Zn.y);
                float Kr = 0.5f * (Zf.y + Zn.y), Ki = -0.5f * (Zf.x - Zn.x);
                sr[q] += Qr * Kr + Qi * Ki;
                si[q] += Qi * Kr - Qr * Ki;
            }
        }
    }
    float* pb = g_part + (size_t)(b * 64 + grp) * 1026;
    #pragma unroll
    for (int q = 0; q < 3; q++) {
        int f = tid + q * 256;
        if (f <= 512) { pb[2 * f] = sr[q]; pb[2 * f + 1] = si[q]; }
    }
}

__global__ void reduce_part_kernel() {
    int idx = blockIdx.x * 256 + threadIdx.x;
    if (idx >= Bb * 1026) return;
    int b = idx / 1026, r = idx % 1026;
    float s = 0.f;
    const float* p = g_part + (size_t)b * 64 * 1026 + r;
    #pragma unroll 4
    for (int g = 0; g < 64; g++) s += p[(size_t)g * 1026];
    g_sf[idx] = s;
}

__global__ __launch_bounds__(128) void invtopk_kernel() {
    int b = blockIdx.x, tid = threadIdx.x;
    __shared__ float2 z[1024];
    __shared__ float2 tw[512];
    __shared__ float mc[1024];
    __shared__ float rv[128];
    __shared__ int   ri[128];
    __shared__ float topv[TOPK];
    fill_twiddle(tw, tid, 128);
    for (int i = tid; i < 1024; i += 128) {
        int r = __brev((unsigned)i) >> 22;
        float2 v;
        if (i <= 512)
            v = make_float2(g_sf[b * 1026 + 2 * i], -g_sf[b * 1026 + 2 * i + 1]);
        else {
            int f2 = 1024 - i;
            v = make_float2(g_sf[b * 1026 + 2 * f2], g_sf[b * 1026 + 2 * f2 + 1]);
        }
        z[r] = v;
    }
    __syncthreads();
    fft1024_inplace(z, tw, tid, 128);
    const float norm = 1.f / (1024.f * 512.f);
    for (int i = tid; i < 1024; i += 128) mc[i] = z[i].x * norm;
    __syncthreads();
    for (int kk = 0; kk < TOPK; kk++) {
        float bv = -FLT_MAX; int bi = 1 << 30;
        for (int i = tid; i < 1024; i += 128) {
            float v = mc[i];
            if (v > bv || (v == bv && i < bi)) { bv = v; bi = i; }
        }
        rv[tid] = bv; ri[tid] = bi; __syncthreads();
        for (int o = 64; o; o >>= 1) {
            if (tid < o) {
                if (rv[tid + o] > rv[tid] || (rv[tid + o] == rv[tid] && ri[tid + o] < ri[tid])) {
                    rv[tid] = rv[tid + o]; ri[tid] = ri[tid + o];
                }
            }
            __syncthreads();
        }
        if (tid == 0) {
            topv[kk] = rv[0];
            g_delay[b * TOPK + kk] = ri[0];
            mc[ri[0]] = -FLT_MAX;
        }
        __syncthreads();
    }
    if (tid == 0) {
        float mx = -FLT_MAX;
        for (int k = 0; k < TOPK; k++) mx = fmaxf(mx, topv[k]);
        float s = 0.f, e[TOPK];
        for (int k = 0; k < TOPK; k++) { e[k] = expf(topv[k] - mx); s += e[k]; }
        float invs = 1.f / s;
        for (int k = 0; k < TOPK; k++) g_wt[b * TOPK + k] = e[k] * invs;
    }
}

// ------------------------- delay aggregation (on H, emits bf16 split) -----
__global__ __launch_bounds__(128) void agg_kernel(const float* __restrict__ v) {
    int bt = blockIdx.x;
    int b = bt >> 10, t = bt & 1023;
    __shared__ float ws[TOPK];
    __shared__ int   ds[TOPK];
    if (threadIdx.x < TOPK) {
        ws[threadIdx.x] = g_wt[b * TOPK + threadIdx.x];
        ds[threadIdx.x] = g_delay[b * TOPK + threadIdx.x];
    }
    __syncthreads();
    const float4* vp = (const float4*)v + (size_t)b * Tt * 128;
    float4 acc = make_float4(0.f, 0.f, 0.f, 0.f);
    #pragma unroll
    for (int i = 0; i < TOPK; i++) {
        int src = t + ds[i]; if (src >= Tt) src -= Tt;
        float4 r = vp[src * 128 + threadIdx.x];
        float w = ws[i];
        acc.x += w * r.x; acc.y += w * r.y; acc.z += w * r.z; acc.w += w * r.w;
    }
    store_split4(acc, ((size_t)bt * 128 + threadIdx.x) * 4);
}

// ------------------------- head (reduces mean partials) -------------------
__global__ __launch_bounds__(256) void head_kernel(const float* __restrict__ w1, const float* __restrict__ b1,
                            const float* __restrict__ w2, const float* __restrict__ b2,
                            float* __restrict__ out) {
    int b = blockIdx.x;
    __shared__ float fs[Dd];
    __shared__ float hs[FCH];
    for (int i = threadIdx.x; i < Dd; i += 256) {
        float s = 0.f;
        #pragma unroll
        for (int w = 0; w < 16; w++) s += g_part[(size_t)(b * 16 + w) * Dd + i];
        fs[i] = s * (1.f / (float)Tt);
    }
    __syncthreads();
    float a = b1[threadIdx.x];
    for (int i = 0; i < Dd; i++) a += fs[i] * w1[i * FCH + threadIdx.x];
    hs[threadIdx.x] = fmaxf(a, 0.f);
    __syncthreads();
    if (threadIdx.x < NCLS) {
        float o = b2[threadIdx.x];
        for (int j = 0; j < FCH; j++) o += hs[j] * w2[j * NCLS + threadIdx.x];
        out[b * NCLS + threadIdx.x] = o;
    }
}

// ------------------------- host orchestration ----------------------------
extern "C" void kernel_launch(void* const* d_in, const int* in_sizes, int n_in,
                              void* d_out, int out_size) {
    const float* x      = (const float*)d_in[0];
    const float* emb_w  = (const float*)d_in[1];
    const float* emb_g  = (const float*)d_in[2];
    const float* emb_b  = (const float*)d_in[3];
    const float* attn_w = (const float*)d_in[4];
    const float* attn_b = (const float*)d_in[5];
    const float* ln_g   = (const float*)d_in[6];
    const float* ln_b   = (const float*)d_in[7];
    const float* fc1w   = (const float*)d_in[8];
    const float* fc1b   = (const float*)d_in[9];
    const float* fc2w   = (const float*)d_in[10];
    const float* fc2b   = (const float*)d_in[11];
    const float* hw1    = (const float*)d_in[12];
    const float* hb1    = (const float*)d_in[13];
    const float* hw2    = (const float*)d_in[14];
    const float* hb2    = (const float*)d_in[15];
    float* out = (float*)d_out;

    float *H, *A, *Bq, *Cv, *QT, *KT, *F;
    __nv_bfloat16 *AH, *AL, *WH, *WL;
    float *BQK, *BVO;
    cudaGetSymbolAddress((void**)&H,  g_h);
    cudaGetSymbolAddress((void**)&A,  g_a);
    cudaGetSymbolAddress((void**)&Bq, g_b);
    cudaGetSymbolAddress((void**)&Cv, g_c);
    cudaGetSymbolAddress((void**)&QT, g_qt);
    cudaGetSymbolAddress((void**)&KT, g_kt);
    cudaGetSymbolAddress((void**)&F,  g_ffn);
    cudaGetSymbolAddress((void**)&AH, g_ah);
    cudaGetSymbolAddress((void**)&AL, g_al);
    cudaGetSymbolAddress((void**)&WH, g_wh);
    cudaGetSymbolAddress((void**)&WL, g_wl);
    cudaGetSymbolAddress((void**)&BQK, g_bqk);
    cudaGetSymbolAddress((void**)&BVO, g_bvo);
    __nv_bfloat16* FH = (__nv_bfloat16*)F;
    __nv_bfloat16* FL = FH + (size_t)Mrows * FFNN;

    cudaFuncSetAttribute(gemm_bf16<0,1,0,3>, cudaFuncAttributeMaxDynamicSharedMemorySize, GSMEM);
    cudaFuncSetAttribute(gemm_bf16<1,0,1,3>, cudaFuncAttributeMaxDynamicSharedMemorySize, GSMEM);
    cudaFuncSetAttribute(gemm_bf16<0,1,0,2>, cudaFuncAttributeMaxDynamicSharedMemorySize, GSMEM);
    cudaFuncSetAttribute(gemm_bf16<1,0,1,2>, cudaFuncAttributeMaxDynamicSharedMemorySize, GSMEM);
    cudaFuncSetAttribute(gemm_qk, cudaFuncAttributeMaxDynamicSharedMemorySize, QK_SMEM);

    // launch order: posscale(0), embed(1), prep(2), gemm_qk(3) <- ncu slot
    posscale_kernel<<<2048 + 96, 256>>>(x);
    embed_kernel<<<Bb * Tt, 128>>>(x, emb_w, emb_g, emb_b);
    prep_kernel<<<Ll * 2817, dim3(32, 8)>>>(attn_w, attn_b, fc1w, fc2w, WH, WL);

    dim3 gQ(Dd / 128, Mrows / 128);
    dim3 gQK(1024 / 128, Mrows / 128);
    dim3 gF(FFNN / 128, Mrows / 128);

    for (int l = 0; l < Ll; l++) {
        size_t lb = (size_t)l * LW;
        const float* lg0 = ln_g + (size_t)(l * 2 + 0) * Dd;
        const float* lb0 = ln_b + (size_t)(l * 2 + 0) * Dd;
        const float* lg1 = ln_g + (size_t)(l * 2 + 1) * Dd;
        const float* lb1 = ln_b + (size_t)(l * 2 + 1) * Dd;

        // merged Q,K 3-split GEMM with fused transposed (B,D,T) output
        gemm_qk<<<gQK, 256, QK_SMEM>>>(AH, AL, WH + lb + OFF_QK, WL + lb + OFF_QK,
                                       BQK + l * 1024, QT, KT);

        fft_corr_kernel<<<Bb * 64, 256>>>();
        reduce_part_kernel<<<(Bb * 1026 + 255) / 256, 256>>>();
        invtopk_kernel<<<Bb, 128>>>();

        agg_kernel<<<Bb * Tt, 128>>>(H);

        const float* f1b = fc1b + (size_t)l * FFNN;
        const float* f2b = fc2b + (size_t)l * Dd;

        if (l < Ll - 1) {
            // layer feeds next layer's selection: full 3-pass precision
            gemm_bf16<0,1,0,3><<<gQ, 256, GSMEM>>>(AH, AL, WH + lb + OFF_WVO, WL + lb + OFF_WVO,
                                                   BVO + l * Dd, H, Bq, nullptr, nullptr, Mrows, Dd, Dd);
            ln_decomp_kernel<0><<<dim3(Bb, Tt / 64), 128>>>(Bq, lg0, lb0, Cv);
            gemm_bf16<1,0,1,3><<<gF, 256, GSMEM>>>(AH, AL, WH + lb + OFF_FC1, WL + lb + OFF_FC1,
                                                   f1b, nullptr, nullptr, FH, FL, Mrows, FFNN, Dd);
            gemm_bf16<0,1,0,3><<<gQ, 256, GSMEM>>>(FH, FL, WH + lb + OFF_FC2, WL + lb + OFF_FC2,
                                                   f2b, Cv, A, nullptr, nullptr, Mrows, Dd, FFNN);
            ln_decomp_kernel<0><<<dim3(Bb, Tt / 64), 128>>>(A, lg1, lb1, H);
        } else {
            // last layer: continuous path to output only -> 2-pass (drop B-low)
            gemm_bf16<0,1,0,2><<<gQ, 256, GSMEM>>>(AH, AL, WH + lb + OFF_WVO, WL + lb + OFF_WVO,
                                                   BVO + l * Dd, H, Bq, nullptr, nullptr, Mrows, Dd, Dd);
            ln_decomp_kernel<0><<<dim3(Bb, Tt / 64), 128>>>(Bq, lg0, lb0, Cv);
            gemm_bf16<1,0,1,2><<<gF, 256, GSMEM>>>(AH, AL, WH + lb + OFF_FC1, WL + lb + OFF_FC1,
                                                   f1b, nullptr, nullptr, FH, FL, Mrows, FFNN, Dd);
            gemm_bf16<0,1,0,2><<<gQ, 256, GSMEM>>>(FH, FL, WH + lb + OFF_FC2, WL + lb + OFF_FC2,
                                                   f2b, Cv, A, nullptr, nullptr, Mrows, Dd, FFNN);
            ln_decomp_kernel<1><<<dim3(Bb, Tt / 64), 128>>>(A, lg1, lb1, H);  // + mean partials
        }
    }

    head_kernel<<<Bb, 256>>>(hw1, hb1, hw2, hb2, out);
}

// round 17
// speedup vs baseline: 1.4307x; 1.4307x over previous
#include <cuda_runtime.h>
#include <cuda_bf16.h>
#include <math.h>
#include <float.h>
#include <stdint.h>

#define Bb 64
#define Tt 1024
#define Cc 12
#define Dd 512
#define Ll 2
#define FFNN 2048
#define FCH 256
#define NCLS 5
#define TOPK 20
#define LNEPS 1e-5f
#define Mrows (Bb*Tt)

// ------------------------- scratch (device globals; no allocs allowed) ----
__device__ float g_h [Bb*Tt*Dd];
__device__ float g_a [Bb*Tt*Dd];
__device__ float g_b [Bb*Tt*Dd];
__device__ float g_c [Bb*Tt*Dd];
__device__ float g_qt[Bb*Tt*Dd];
__device__ float g_kt[Bb*Tt*Dd];
__device__ float g_ffn[(size_t)Bb*Tt*FFNN];   // fc1 bf16 hi/lo
__device__ float g_part[Bb*64*1026];          // fft partials; also meanT partials
__device__ float g_sf[Bb*1026];
__device__ int   g_delay[Bb*TOPK];
__device__ float g_wt[Bb*TOPK];
__device__ float g_scale[Bb*Cc];
__device__ float g_pos[Tt*Dd];
__device__ float g_bqk[Ll][1024];
__device__ float g_bvo[Ll][Dd];
// bf16 split buffers (activations) and weights
__device__ __nv_bfloat16 g_ah[(size_t)Mrows*Dd];
__device__ __nv_bfloat16 g_al[(size_t)Mrows*Dd];
__device__ __nv_bfloat16 g_wh[8*1024*1024];
__device__ __nv_bfloat16 g_wl[8*1024*1024];

// ------------------------- helpers ---------------------------------------
__device__ __forceinline__ uint32_t smem_u32(const void* p) {
    uint32_t a;
    asm("{ .reg .u64 t; cvta.to.shared.u64 t, %1; cvt.u32.u64 %0, t; }" : "=r"(a) : "l"(p));
    return a;
}
__device__ __forceinline__ void cpasync16(uint32_t sa, const void* ga) {
    asm volatile("cp.async.cg.shared.global [%0], [%1], 16;\n"
        :: "r"(sa), "l"(__cvta_generic_to_global(ga)));
}
#define CP_COMMIT() asm volatile("cp.async.commit_group;\n" ::: "memory")
#define CP_WAIT(n)  asm volatile("cp.async.wait_group %0;\n" :: "n"(n) : "memory")

__device__ __forceinline__ void mma16816(float (&d)[4], const uint32_t (&a)[4], const uint32_t (&b)[2]) {
    asm volatile("mma.sync.aligned.m16n8k16.row.col.f32.bf16.bf16.f32 "
        "{%0,%1,%2,%3}, {%4,%5,%6,%7}, {%8,%9}, {%0,%1,%2,%3};\n"
        : "+f"(d[0]), "+f"(d[1]), "+f"(d[2]), "+f"(d[3])
        : "r"(a[0]), "r"(a[1]), "r"(a[2]), "r"(a[3]), "r"(b[0]), "r"(b[1]));
}
__device__ __forceinline__ void lds_a(uint32_t (&a)[4][4], uint32_t base, int wm0, int lane, int h) {
    uint32_t addr = base + (uint32_t)((wm0 + (lane & 15)) * 80 + ((h << 1) + (lane >> 4)) * 16);
    #pragma unroll
    for (int i = 0; i < 4; i++) {
        asm volatile("ldmatrix.sync.aligned.m8n8.x4.shared.b16 {%0,%1,%2,%3}, [%4];\n"
            : "=r"(a[i][0]), "=r"(a[i][1]), "=r"(a[i][2]), "=r"(a[i][3])
            : "r"(addr + i * 16 * 80));
    }
}
__device__ __forceinline__ void lds_b(uint32_t (&b)[4][2], uint32_t base, int wn0, int lane, int h) {
    uint32_t addr = base + (uint32_t)((wn0 + (lane & 7)) * 80 + ((h << 1) + ((lane >> 3) & 1)) * 16);
    #pragma unroll
    for (int j = 0; j < 4; j++) {
        asm volatile("ldmatrix.sync.aligned.m8n8.x2.shared.b16 {%0,%1}, [%2];\n"
            : "=r"(b[j][0]), "=r"(b[j][1]) : "r"(addr + j * 8 * 80));
    }
}
// fp32 float4 -> bf16 hi/lo split store into g_ah/g_al at element offset eo
__device__ __forceinline__ void store_split4(float4 o, size_t eo) {
    __nv_bfloat16 h0 = __float2bfloat16_rn(o.x), h1 = __float2bfloat16_rn(o.y);
    __nv_bfloat16 h2 = __float2bfloat16_rn(o.z), h3 = __float2bfloat16_rn(o.w);
    __nv_bfloat16 l0 = __float2bfloat16_rn(o.x - __bfloat162float(h0));
    __nv_bfloat16 l1 = __float2bfloat16_rn(o.y - __bfloat162float(h1));
    __nv_bfloat16 l2 = __float2bfloat16_rn(o.z - __bfloat162float(h2));
    __nv_bfloat16 l3 = __float2bfloat16_rn(o.w - __bfloat162float(h3));
    *(__nv_bfloat162*)(g_ah + eo)     = __nv_bfloat162(h0, h1);
    *(__nv_bfloat162*)(g_ah + eo + 2) = __nv_bfloat162(h2, h3);
    *(__nv_bfloat162*)(g_al + eo)     = __nv_bfloat162(l0, l1);
    *(__nv_bfloat162*)(g_al + eo + 2) = __nv_bfloat162(l2, l3);
}

// ------------------------- merged pos + scale ------------------------------
__global__ void posscale_kernel(const float* __restrict__ x) {
    if (blockIdx.x < 2048) {
        int idx = blockIdx.x * 256 + threadIdx.x;
        int t = idx / Dd, d = idx % Dd;
        int j = (d < 256) ? d : d - 256;
        double freq = exp(-(double)j * (log(10000.0) / 256.0));
        double arg = (double)t * freq;
        g_pos[idx] = (float)((d < 256) ? sin(arg) : cos(arg));
    } else {
        int pair = (blockIdx.x - 2048) * 8 + (threadIdx.x >> 5);
        int lane = threadIdx.x & 31;
        int b = pair / Cc, c = pair % Cc;
        float s = 0.f;
        for (int t = lane; t < Tt; t += 32)
            s += fabsf(x[(b * Tt + t) * Cc + c]);
        for (int o = 16; o; o >>= 1) s += __shfl_down_sync(0xffffffffu, s, o);
        if (lane == 0) g_scale[b * Cc + c] = fmaxf(s / Tt, 1e-10f);
    }
}

// ------------------------- consolidated weight prep -----------------------
#define LW       2883584
#define OFF_QK   0
#define OFF_WVO  524288
#define OFF_FC1  786432
#define OFF_FC2  1835008
__global__ void prep_kernel(const float* __restrict__ attn_w, const float* __restrict__ attn_b,
                            const float* __restrict__ fc1w, const float* __restrict__ fc2w,
                            __nv_bfloat16* __restrict__ WHp, __nv_bfloat16* __restrict__ WLp) {
    __shared__ float tile[32][33];
    int bid = blockIdx.x;
    int l = bid / 2817, r = bid % 2817;
    size_t lb = (size_t)l * LW;
    int tx = threadIdx.x, ty = threadIdx.y;
    int tid = ty * 32 + tx;
    const float* Wv = attn_w + (size_t)(l * 4 + 2) * Dd * Dd;
    const float* Wo = attn_w + (size_t)(l * 4 + 3) * Dd * Dd;

    if (r == 2816) {  // bias prep
        const float* bq = attn_b + (size_t)(l * 4 + 0) * Dd;
        const float* bk = attn_b + (size_t)(l * 4 + 1) * Dd;
        const float* bv = attn_b + (size_t)(l * 4 + 2) * Dd;
        const float* bo = attn_b + (size_t)(l * 4 + 3) * Dd;
        #pragma unroll
        for (int q = 0; q < 2; q++) {
            int n = tid + q * 256;
            float s = 0.f;
            for (int k = 0; k < Dd; k++) s += bv[k] * Wo[k * Dd + n];
            g_bvo[l][n] = s + bo[n];
            g_bqk[l][n] = bq[n];
            g_bqk[l][n + Dd] = bk[n];
        }
        return;
    }

    const float* src = nullptr; __nv_bfloat16 *oh, *ol;
    int K, N, t;
    bool compute_wvo = false;
    if (r < 256) {
        src = attn_w + (size_t)(l * 4 + 0) * Dd * Dd; oh = WHp + lb + OFF_QK; ol = WLp + lb + OFF_QK;
        K = Dd; N = Dd; t = r;
    } else if (r < 512) {
        src = attn_w + (size_t)(l * 4 + 1) * Dd * Dd; oh = WHp + lb + OFF_QK + Dd * Dd; ol = WLp + lb + OFF_QK + Dd * Dd;
        K = Dd; N = Dd; t = r - 256;
    } else if (r < 768) {
        oh = WHp + lb + OFF_WVO; ol = WLp + lb + OFF_WVO;
        K = Dd; N = Dd; t = r - 512; compute_wvo = true;
    } else if (r < 1792) {
        src = fc1w + (size_t)l * Dd * FFNN; oh = WHp + lb + OFF_FC1; ol = WLp + lb + OFF_FC1;
        K = Dd; N = FFNN; t = r - 768;
    } else {
        src = fc2w + (size_t)l * FFNN * Dd; oh = WHp + lb + OFF_FC2; ol = WLp + lb + OFF_FC2;
        K = FFNN; N = Dd; t = r - 1792;
    }
    int nt = N / 32;
    int n0 = (t % nt) * 32, k0 = (t / nt) * 32;

    if (compute_wvo) {
        float s[4] = {0.f, 0.f, 0.f, 0.f};
        for (int k = 0; k < Dd; k++) {
            float wo = Wo[k * Dd + n0 + tx];
            #pragma unroll
            for (int q = 0; q < 4; q++)
                s[q] += Wv[(size_t)(k0 + ty + 8 * q) * Dd + k] * wo;
        }
        #pragma unroll
        for (int q = 0; q < 4; q++) tile[ty + 8 * q][tx] = s[q];
    } else {
        for (int i = ty; i < 32; i += 8)
            tile[i][tx] = src[(size_t)(k0 + i) * N + n0 + tx];
    }
    __syncthreads();
    for (int i = ty; i < 32; i += 8) {
        float v = tile[tx][i];
        __nv_bfloat16 h = __float2bfloat16_rn(v);
        size_t o = (size_t)(n0 + i) * K + k0 + tx;
        oh[o] = h;
        ol[o] = __float2bfloat16_rn(v - __bfloat162float(h));
    }
}

// ------------------------- bf16 mma.sync GEMM (3-split) -------------------
#define TILEB 10240            // 128 rows * 80 bytes
#define STAGEB (4*TILEB)       // Ah, Al, Bh, Bl
#define GSMEM  (2*STAGEB)      // 81920
template<int ACT, int RES, int OUTBF>
__global__ __launch_bounds__(256, 2) void gemm_bf16(
        const __nv_bfloat16* __restrict__ Ah, const __nv_bfloat16* __restrict__ Al,
        const __nv_bfloat16* __restrict__ Bh, const __nv_bfloat16* __restrict__ Bl,
        const float* __restrict__ bias, const float* __restrict__ res,
        float* __restrict__ C, __nv_bfloat16* __restrict__ Ch, __nv_bfloat16* __restrict__ Cl,
        int M, int N, int K) {
    extern __shared__ char smem[];
    uint32_t sb = smem_u32(smem);
    int tid = threadIdx.x, lane = tid & 31, wid = tid >> 5;
    int m0 = blockIdx.y * 128, n0 = blockIdx.x * 128;
    int wm0 = (wid & 1) * 64, wn0 = (wid >> 1) * 32;

    float acc[4][4][4];
    #pragma unroll
    for (int i = 0; i < 4; i++)
        #pragma unroll
        for (int j = 0; j < 4; j++)
            #pragma unroll
            for (int r = 0; r < 4; r++) acc[i][j][r] = 0.f;

    const __nv_bfloat16* g0 = Ah + (size_t)m0 * K;
    const __nv_bfloat16* g1 = Al + (size_t)m0 * K;
    const __nv_bfloat16* g2 = Bh + (size_t)n0 * K;
    const __nv_bfloat16* g3 = Bl + (size_t)n0 * K;
    int lrow = tid >> 2;
    int lchB = (tid & 3) * 16;
    int lchE = (tid & 3) * 8;

    int NC = K >> 5;
    {
        uint32_t sb0 = sb + lrow * 80 + lchB;
        size_t go = (size_t)lrow * K + lchE;
        size_t go2 = go + (size_t)64 * K;
        cpasync16(sb0,                       g0 + go);
        cpasync16(sb0 + 64*80,               g0 + go2);
        cpasync16(sb0 + TILEB,               g1 + go);
        cpasync16(sb0 + TILEB + 64*80,       g1 + go2);
        cpasync16(sb0 + 2*TILEB,             g2 + go);
        cpasync16(sb0 + 2*TILEB + 64*80,     g2 + go2);
        cpasync16(sb0 + 3*TILEB,             g3 + go);
        cpasync16(sb0 + 3*TILEB + 64*80,     g3 + go2);
        CP_COMMIT();
    }
    for (int c = 0; c < NC; c++) {
        if (c + 1 < NC) {
            uint32_t sb1 = sb + ((c + 1) & 1) * STAGEB + lrow * 80 + lchB;
            size_t go = (size_t)lrow * K + (size_t)(c + 1) * 32 + lchE;
            size_t go2 = go + (size_t)64 * K;
            cpasync16(sb1,                   g0 + go);
            cpasync16(sb1 + 64*80,           g0 + go2);
            cpasync16(sb1 + TILEB,           g1 + go);
            cpasync16(sb1 + TILEB + 64*80,   g1 + go2);
            cpasync16(sb1 + 2*TILEB,         g2 + go);
            cpasync16(sb1 + 2*TILEB + 64*80, g2 + go2);
            cpasync16(sb1 + 3*TILEB,         g3 + go);
            cpasync16(sb1 + 3*TILEB + 64*80, g3 + go2);
            CP_COMMIT();
            CP_WAIT(1);
        } else {
            CP_WAIT(0);
        }
        __syncthreads();
        uint32_t Ahb = sb + (c & 1) * STAGEB;
        uint32_t Alb = Ahb + TILEB, Bhb = Ahb + 2*TILEB, Blb = Ahb + 3*TILEB;
        #pragma unroll
        for (int h = 0; h < 2; h++) {
            uint32_t af[4][4], bfh[4][2], bfl[4][2];
            lds_a(af, Ahb, wm0, lane, h);
            lds_b(bfh, Bhb, wn0, lane, h);
            #pragma unroll
            for (int i = 0; i < 4; i++)
                #pragma unroll
                for (int j = 0; j < 4; j++) mma16816(acc[i][j], af[i], bfh[j]);
            lds_b(bfl, Blb, wn0, lane, h);
            #pragma unroll
            for (int i = 0; i < 4; i++)
                #pragma unroll
                for (int j = 0; j < 4; j++) mma16816(acc[i][j], af[i], bfl[j]);
            lds_a(af, Alb, wm0, lane, h);
            #pragma unroll
            for (int i = 0; i < 4; i++)
                #pragma unroll
                for (int j = 0; j < 4; j++) mma16816(acc[i][j], af[i], bfh[j]);
        }
        __syncthreads();
    }

    int rb = m0 + wm0 + (lane >> 2);
    int cb = n0 + wn0 + (lane & 3) * 2;
    #pragma unroll
    for (int i = 0; i < 4; i++) {
        #pragma unroll
        for (int j = 0; j < 4; j++) {
            #pragma unroll
            for (int half = 0; half < 2; half++) {
                int r = rb + i * 16 + half * 8;
                int col = cb + j * 8;
                float v0 = acc[i][j][half * 2 + 0] + bias[col];
                float v1 = acc[i][j][half * 2 + 1] + bias[col + 1];
                if (ACT == 1) {
                    v0 = 0.5f * v0 * (1.f + erff(v0 * 0.70710678118654752f));
                    v1 = 0.5f * v1 * (1.f + erff(v1 * 0.70710678118654752f));
                }
                if (RES) {
                    const float2 rr = *(const float2*)&res[(size_t)r * N + col];
                    v0 += rr.x; v1 += rr.y;
                }
                if (OUTBF) {
                    __nv_bfloat16 h0 = __float2bfloat16_rn(v0), h1 = __float2bfloat16_rn(v1);
                    __nv_bfloat16 l0 = __float2bfloat16_rn(v0 - __bfloat162float(h0));
                    __nv_bfloat16 l1 = __float2bfloat16_rn(v1 - __bfloat162float(h1));
                    *(__nv_bfloat162*)&Ch[(size_t)r * N + col] = __nv_bfloat162(h0, h1);
                    *(__nv_bfloat162*)&Cl[(size_t)r * N + col] = __nv_bfloat162(l0, l1);
                } else {
                    *(float2*)&C[(size_t)r * N + col] = make_float2(v0, v1);
                }
            }
        }
    }
}

// ------------------------- QK GEMM: 3-split, transposed (B,D,T) output ----
#define QK_SMEM  (128*129*4 > GSMEM ? 128*129*4 : GSMEM)
__global__ __launch_bounds__(256, 2) void gemm_qk(
        const __nv_bfloat16* __restrict__ Ah, const __nv_bfloat16* __restrict__ Al,
        const __nv_bfloat16* __restrict__ Bh, const __nv_bfloat16* __restrict__ Bl,
        const float* __restrict__ bias, float* __restrict__ Qo, float* __restrict__ Ko) {
    const int K = Dd;
    extern __shared__ char smem[];
    uint32_t sb = smem_u32(smem);
    int tid = threadIdx.x, lane = tid & 31, wid = tid >> 5;
    int m0 = blockIdx.y * 128, n0 = blockIdx.x * 128;
    int wm0 = (wid & 1) * 64, wn0 = (wid >> 1) * 32;

    float acc[4][4][4];
    #pragma unroll
    for (int i = 0; i < 4; i++)
        #pragma unroll
        for (int j = 0; j < 4; j++)
            #pragma unroll
            for (int r = 0; r < 4; r++) acc[i][j][r] = 0.f;

    const __nv_bfloat16* g0 = Ah + (size_t)m0 * K;
    const __nv_bfloat16* g1 = Al + (size_t)m0 * K;
    const __nv_bfloat16* g2 = Bh + (size_t)n0 * K;
    const __nv_bfloat16* g3 = Bl + (size_t)n0 * K;
    int lrow = tid >> 2;
    int lchB = (tid & 3) * 16;
    int lchE = (tid & 3) * 8;

    const int NC = K >> 5;
    {
        uint32_t sb0 = sb + lrow * 80 + lchB;
        size_t go = (size_t)lrow * K + lchE;
        size_t go2 = go + (size_t)64 * K;
        cpasync16(sb0,                       g0 + go);
        cpasync16(sb0 + 64*80,               g0 + go2);
        cpasync16(sb0 + TILEB,               g1 + go);
        cpasync16(sb0 + TILEB + 64*80,       g1 + go2);
        cpasync16(sb0 + 2*TILEB,             g2 + go);
        cpasync16(sb0 + 2*TILEB + 64*80,     g2 + go2);
        cpasync16(sb0 + 3*TILEB,             g3 + go);
        cpasync16(sb0 + 3*TILEB + 64*80,     g3 + go2);
        CP_COMMIT();
    }
    for (int c = 0; c < NC; c++) {
        if (c + 1 < NC) {
            uint32_t sb1 = sb + ((c + 1) & 1) * STAGEB + lrow * 80 + lchB;
            size_t go = (size_t)lrow * K + (size_t)(c + 1) * 32 + lchE;
            size_t go2 = go + (size_t)64 * K;
            cpasync16(sb1,                   g0 + go);
            cpasync16(sb1 + 64*80,           g0 + go2);
            cpasync16(sb1 + TILEB,           g1 + go);
            cpasync16(sb1 + TILEB + 64*80,   g1 + go2);
            cpasync16(sb1 + 2*TILEB,         g2 + go);
            cpasync16(sb1 + 2*TILEB + 64*80, g2 + go2);
            cpasync16(sb1 + 3*TILEB,         g3 + go);
            cpasync16(sb1 + 3*TILEB + 64*80, g3 + go2);
            CP_COMMIT();
            CP_WAIT(1);
        } else {
            CP_WAIT(0);
        }
        __syncthreads();
        uint32_t Ahb = sb + (c & 1) * STAGEB;
        uint32_t Alb = Ahb + TILEB, Bhb = Ahb + 2*TILEB, Blb = Ahb + 3*TILEB;
        #pragma unroll
        for (int h = 0; h < 2; h++) {
            uint32_t af[4][4], bfh[4][2], bfl[4][2];
            lds_a(af, Ahb, wm0, lane, h);
            lds_b(bfh, Bhb, wn0, lane, h);
            #pragma unroll
            for (int i = 0; i < 4; i++)
                #pragma unroll
                for (int j = 0; j < 4; j++) mma16816(acc[i][j], af[i], bfh[j]);
            lds_b(bfl, Blb, wn0, lane, h);
            #pragma unroll
            for (int i = 0; i < 4; i++)
                #pragma unroll
                for (int j = 0; j < 4; j++) mma16816(acc[i][j], af[i], bfl[j]);
            lds_a(af, Alb, wm0, lane, h);
            #pragma unroll
            for (int i = 0; i < 4; i++)
                #pragma unroll
                for (int j = 0; j < 4; j++) mma16816(acc[i][j], af[i], bfh[j]);
        }
        __syncthreads();
    }

    // epilogue: bias add -> smem staging (pitch 129) -> transposed store
    float* s = (float*)smem;
    int srow = wm0 + (lane >> 2);
    int scol = wn0 + (lane & 3) * 2;
    #pragma unroll
    for (int i = 0; i < 4; i++) {
        #pragma unroll
        for (int j = 0; j < 4; j++) {
            #pragma unroll
            for (int half = 0; half < 2; half++) {
                int rr = srow + i * 16 + half * 8;
                int cc = scol + j * 8;
                s[rr * 129 + cc]     = acc[i][j][half * 2 + 0] + bias[n0 + cc];
                s[rr * 129 + cc + 1] = acc[i][j][half * 2 + 1] + bias[n0 + cc + 1];
            }
        }
    }
    __syncthreads();
    int b = m0 >> 10, t0 = m0 & 1023;
    int dl = tid >> 1, th = tid & 1;
    int dg = n0 + dl;
    float* dst = (dg < Dd ? Qo + (size_t)(b * Dd + dg) * Tt
                          : Ko + (size_t)(b * Dd + dg - Dd) * Tt) + t0 + th * 64;
    #pragma unroll
    for (int u = 0; u < 64; u += 4) {
        float4 v;
        v.x = s[(th * 64 + u + 0) * 129 + dl];
        v.y = s[(th * 64 + u + 1) * 129 + dl];
        v.z = s[(th * 64 + u + 2) * 129 + dl];
        v.w = s[(th * 64 + u + 3) * 129 + dl];
        *(float4*)(dst + u) = v;
    }
}

// ------------------------- small helpers ---------------------------------
__device__ __forceinline__ float blockReduceSum128(float v, float* sh) {
    sh[threadIdx.x] = v; __syncthreads();
    for (int o = 64; o; o >>= 1) {
        if (threadIdx.x < o) sh[threadIdx.x] += sh[threadIdx.x + o];
        __syncthreads();
    }
    float r = sh[0]; __syncthreads();
    return r;
}

// ------------------------- embedding + pos + LN + split (fused) -----------
__global__ void embed_kernel(const float* __restrict__ x, const float* __restrict__ w,
                             const float* __restrict__ gamma, const float* __restrict__ beta) {
    int bt = blockIdx.x;
    int b = bt >> 10, t = bt & 1023;
    __shared__ float xs[Cc], ls[Cc];
    __shared__ float sh[128];
    if (threadIdx.x < Cc) {
        float sc = g_scale[b * Cc + threadIdx.x];
        xs[threadIdx.x] = x[bt * Cc + threadIdx.x] / sc;
        ls[threadIdx.x] = logf(sc);
    }
    __syncthreads();
    int d0 = threadIdx.x * 4;
    float4 v = *(const float4*)&g_pos[t * Dd + d0];
    #pragma unroll
    for (int c = 0; c < Cc; c++) {
        float xc = xs[c], lc = ls[c];
        float4 w1 = *(const float4*)&w[c * Dd + d0];
        float4 w2 = *(const float4*)&w[(24 + c) * Dd + d0];
        v.x += xc * w1.x + lc * w2.x;
        v.y += xc * w1.y + lc * w2.y;
        v.z += xc * w1.z + lc * w2.z;
        v.w += xc * w1.w + lc * w2.w;
    }
    float s = v.x + v.y + v.z + v.w;
    s = blockReduceSum128(s, sh);
    float mu = s / Dd;
    float dx = v.x - mu, dy = v.y - mu, dz = v.z - mu, dw = v.w - mu;
    float sq = dx * dx + dy * dy + dz * dz + dw * dw;
    sq = blockReduceSum128(sq, sh);
    float rstd = rsqrtf(sq / Dd + LNEPS);
    float4 gg = *(const float4*)&gamma[d0];
    float4 bbv = *(const float4*)&beta[d0];
    float4 o;
    o.x = dx * rstd * gg.x + bbv.x;
    o.y = dy * rstd * gg.y + bbv.y;
    o.z = dz * rstd * gg.z + bbv.z;
    o.w = dw * rstd * gg.w + bbv.w;
    *(float4*)&g_h[(size_t)bt * Dd + d0] = o;
    store_split4(o, (size_t)bt * Dd + d0);
}

// ------------------------- fused LayerNorm + series decomp + split --------
template<int MEAN>
__global__ __launch_bounds__(128) void ln_decomp_kernel(
        const float* __restrict__ in, const float* __restrict__ gamma,
        const float* __restrict__ beta, float* __restrict__ out) {
    int b = blockIdx.x;
    int t0 = blockIdx.y * 64;
    int tid = threadIdx.x, lane = tid & 31, w = tid >> 5;
    __shared__ float smu[89], srs[89];
    const float* ib = in + (size_t)b * Tt * Dd;

    for (int j = w; j < 89; j += 4) {
        int row = t0 - 12 + j; row = row < 0 ? 0 : (row > Tt - 1 ? Tt - 1 : row);
        const float4* rp = (const float4*)(ib + (size_t)row * Dd);
        float s = 0.f, q = 0.f;
        for (int c = lane; c < 128; c += 32) {
            float4 v = rp[c];
            s += v.x + v.y + v.z + v.w;
            q += v.x * v.x + v.y * v.y + v.z * v.z + v.w * v.w;
        }
        for (int o = 16; o; o >>= 1) {
            s += __shfl_down_sync(0xffffffffu, s, o);
            q += __shfl_down_sync(0xffffffffu, q, o);
        }
        if (lane == 0) {
            float mu = s / Dd;
            smu[j] = mu;
            srs[j] = rsqrtf(q / Dd - mu * mu + LNEPS);
        }
    }
    __syncthreads();

    int d0 = tid * 4;
    float4 gg = *(const float4*)&gamma[d0];
    float4 bv = *(const float4*)&beta[d0];
    #define LDN(J, R) { int row = t0 - 12 + (J); row = row < 0 ? 0 : (row > Tt - 1 ? Tt - 1 : row); \
        float4 v = *(const float4*)(ib + (size_t)row * Dd + d0); \
        float mu = smu[J], rs = srs[J]; \
        (R).x = (v.x - mu) * rs * gg.x + bv.x; (R).y = (v.y - mu) * rs * gg.y + bv.y; \
        (R).z = (v.z - mu) * rs * gg.z + bv.z; (R).w = (v.w - mu) * rs * gg.w + bv.w; }
    float4 s = make_float4(0.f, 0.f, 0.f, 0.f);
    for (int j = 0; j < 25; j++) {
        float4 r; LDN(j, r);
        s.x += r.x; s.y += r.y; s.z += r.z; s.w += r.w;
    }
    const float inv = 1.f / 25.f;
    float4 msum = make_float4(0.f, 0.f, 0.f, 0.f);
    for (int t = 0; t < 64; t++) {
        int j = 12 + t;
        float4 xv; LDN(j, xv);
        float4 o;
        o.x = xv.x - s.x * inv; o.y = xv.y - s.y * inv;
        o.z = xv.z - s.z * inv; o.w = xv.w - s.w * inv;
        size_t eo = (size_t)(b * Tt + t0 + t) * Dd + d0;
        *(float4*)&out[eo] = o;
        store_split4(o, eo);
        if (MEAN) {
            msum.x += o.x; msum.y += o.y; msum.z += o.z; msum.w += o.w;
        }
        if (t < 63) {
            float4 ra, rr;
            LDN(j + 13, ra);
            LDN(j - 12, rr);
            s.x += ra.x - rr.x; s.y += ra.y - rr.y;
            s.z += ra.z - rr.z; s.w += ra.w - rr.w;
        }
    }
    #undef LDN
    if (MEAN)
        *(float4*)&g_part[(size_t)(b * 16 + blockIdx.y) * Dd + d0] = msum;
}

// ------------------------- 1024-pt FFT core (thread-count parametric) -----
__device__ __forceinline__ void fft1024_inplace(float2* z, const float2* tw, int tid, int nthr) {
    #pragma unroll
    for (int s = 1; s <= 10; s++) {
        int half = 1 << (s - 1);
        for (int bf = tid; bf < 512; bf += nthr) {
            int pos = bf & (half - 1);
            int i1 = ((bf >> (s - 1)) << s) + pos;
            float2 w = tw[pos << (10 - s)];
            float2 u = z[i1], v = z[i1 + half];
            float trr = w.x * v.x - w.y * v.y;
            float tii = w.x * v.y + w.y * v.x;
            z[i1]        = make_float2(u.x + trr, u.y + tii);
            z[i1 + half] = make_float2(u.x - trr, u.y - tii);
        }
        __syncthreads();
    }
}

__device__ __forceinline__ void fill_twiddle(float2* tw, int tid, int nthr) {
    for (int j = tid; j < 512; j += nthr) {
        float sn, cs;
        sincosf(-6.283185307179586477f * (float)j / 1024.f, &sn, &cs);
        tw[j] = make_float2(cs, sn);
    }
}

// q,k packed FFT -> cross-spectrum partials; 8 channels per block; 256 thr
__global__ __launch_bounds__(256) void fft_corr_kernel() {
    int bx = blockIdx.x;
    int b = bx >> 6, grp = bx & 63;
    __shared__ float2 z[1024];
    __shared__ float2 tw[512];
    int tid = threadIdx.x;
    fill_twiddle(tw, tid, 256);
    float sr[3], si[3];
    #pragma unroll
    for (int q = 0; q < 3; q++) { sr[q] = 0.f; si[q] = 0.f; }
    const float* qbase = g_qt + (size_t)(b * Dd + grp * 8) * Tt;
    const float* kbase = g_kt + (size_t)(b * Dd + grp * 8) * Tt;
    for (int ch = 0; ch < 8; ch++) {
        __syncthreads();
        for (int i = tid; i < 1024; i += 256) {
            int r = __brev((unsigned)i) >> 22;
            z[r] = make_float2(qbase[ch * Tt + i], kbase[ch * Tt + i]);
        }
        __syncthreads();
        fft1024_inplace(z, tw, tid, 256);
        #pragma unroll
        for (int q = 0; q < 3; q++) {
            int f = tid + q * 256;
            if (f <= 512) {
                float2 Zf = z[f];
                float2 Zn = z[(1024 - f) & 1023];
                float Qr = 0.5f * (Zf.x + Zn.x), Qi = 0.5f * (Zf.y - Zn.y);
                float Kr = 0.5f * (Zf.y + Zn.y), Ki = -0.5f * (Zf.x - Zn.x);
                sr[q] += Qr * Kr + Qi * Ki;
                si[q] += Qi * Kr - Qr * Ki;
            }
        }
    }
    float* pb = g_part + (size_t)(b * 64 + grp) * 1026;
    #pragma unroll
    for (int q = 0; q < 3; q++) {
        int f = tid + q * 256;
        if (f <= 512) { pb[2 * f] = sr[q]; pb[2 * f + 1] = si[q]; }
    }
}

__global__ void reduce_part_kernel() {
    int idx = blockIdx.x * 256 + threadIdx.x;
    if (idx >= Bb * 1026) return;
    int b = idx / 1026, r = idx % 1026;
    float s = 0.f;
    const float* p = g_part + (size_t)b * 64 * 1026 + r;
    #pragma unroll 4
    for (int g = 0; g < 64; g++) s += p[(size_t)g * 1026];
    g_sf[idx] = s;
}

__global__ __launch_bounds__(128) void invtopk_kernel() {
    int b = blockIdx.x, tid = threadIdx.x;
    __shared__ float2 z[1024];
    __shared__ float2 tw[512];
    __shared__ float mc[1024];
    __shared__ float rv[128];
    __shared__ int   ri[128];
    __shared__ float topv[TOPK];
    fill_twiddle(tw, tid, 128);
    for (int i = tid; i < 1024; i += 128) {
        int r = __brev((unsigned)i) >> 22;
        float2 v;
        if (i <= 512)
            v = make_float2(g_sf[b * 1026 + 2 * i], -g_sf[b * 1026 + 2 * i + 1]);
        else {
            int f2 = 1024 - i;
            v = make_float2(g_sf[b * 1026 + 2 * f2], g_sf[b * 1026 + 2 * f2 + 1]);
        }
        z[r] = v;
    }
    __syncthreads();
    fft1024_inplace(z, tw, tid, 128);
    const float norm = 1.f / (1024.f * 512.f);
    for (int i = tid; i < 1024; i += 128) mc[i] = z[i].x * norm;
    __syncthreads();
    for (int kk = 0; kk < TOPK; kk++) {
        float bv = -FLT_MAX; int bi = 1 << 30;
        for (int i = tid; i < 1024; i += 128) {
            float v = mc[i];
            if (v > bv || (v == bv && i < bi)) { bv = v; bi = i; }
        }
        rv[tid] = bv; ri[tid] = bi; __syncthreads();
        for (int o = 64; o; o >>= 1) {
            if (tid < o) {
                if (rv[tid + o] > rv[tid] || (rv[tid + o] == rv[tid] && ri[tid + o] < ri[tid])) {
                    rv[tid] = rv[tid + o]; ri[tid] = ri[tid + o];
                }
            }
            __syncthreads();
        }
        if (tid == 0) {
            topv[kk] = rv[0];
            g_delay[b * TOPK + kk] = ri[0];
            mc[ri[0]] = -FLT_MAX;
        }
        __syncthreads();
    }
    if (tid == 0) {
        float mx = -FLT_MAX;
        for (int k = 0; k < TOPK; k++) mx = fmaxf(mx, topv[k]);
        float s = 0.f, e[TOPK];
        for (int k = 0; k < TOPK; k++) { e[k] = expf(topv[k] - mx); s += e[k]; }
        float invs = 1.f / s;
        for (int k = 0; k < TOPK; k++) g_wt[b * TOPK + k] = e[k] * invs;
    }
}

// ------------------------- delay aggregation (on H, emits bf16 split) -----
__global__ __launch_bounds__(128) void agg_kernel(const float* __restrict__ v) {
    int bt = blockIdx.x;
    int b = bt >> 10, t = bt & 1023;
    __shared__ float ws[TOPK];
    __shared__ int   ds[TOPK];
    if (threadIdx.x < TOPK) {
        ws[threadIdx.x] = g_wt[b * TOPK + threadIdx.x];
        ds[threadIdx.x] = g_delay[b * TOPK + threadIdx.x];
    }
    __syncthreads();
    const float4* vp = (const float4*)v + (size_t)b * Tt * 128;
    float4 acc = make_float4(0.f, 0.f, 0.f, 0.f);
    #pragma unroll
    for (int i = 0; i < TOPK; i++) {
        int src = t + ds[i]; if (src >= Tt) src -= Tt;
        float4 r = vp[src * 128 + threadIdx.x];
        float w = ws[i];
        acc.x += w * r.x; acc.y += w * r.y; acc.z += w * r.z; acc.w += w * r.w;
    }
    store_split4(acc, ((size_t)bt * 128 + threadIdx.x) * 4);
}

// ------------------------- head (reduces mean partials) -------------------
__global__ __launch_bounds__(256) void head_kernel(const float* __restrict__ w1, const float* __restrict__ b1,
                            const float* __restrict__ w2, const float* __restrict__ b2,
                            float* __restrict__ out) {
    int b = blockIdx.x;
    __shared__ float fs[Dd];
    __shared__ float hs[FCH];
    for (int i = threadIdx.x; i < Dd; i += 256) {
        float s = 0.f;
        #pragma unroll
        for (int w = 0; w < 16; w++) s += g_part[(size_t)(b * 16 + w) * Dd + i];
        fs[i] = s * (1.f / (float)Tt);
    }
    __syncthreads();
    float a = b1[threadIdx.x];
    for (int i = 0; i < Dd; i++) a += fs[i] * w1[i * FCH + threadIdx.x];
    hs[threadIdx.x] = fmaxf(a, 0.f);
    __syncthreads();
    if (threadIdx.x < NCLS) {
        float o = b2[threadIdx.x];
        for (int j = 0; j < FCH; j++) o += hs[j] * w2[j * NCLS + threadIdx.x];
        out[b * NCLS + threadIdx.x] = o;
    }
}

// ------------------------- host orchestration ----------------------------
extern "C" void kernel_launch(void* const* d_in, const int* in_sizes, int n_in,
                              void* d_out, int out_size) {
    const float* x      = (const float*)d_in[0];
    const float* emb_w  = (const float*)d_in[1];
    const float* emb_g  = (const float*)d_in[2];
    const float* emb_b  = (const float*)d_in[3];
    const float* attn_w = (const float*)d_in[4];
    const float* attn_b = (const float*)d_in[5];
    const float* ln_g   = (const float*)d_in[6];
    const float* ln_b   = (const float*)d_in[7];
    const float* fc1w   = (const float*)d_in[8];
    const float* fc1b   = (const float*)d_in[9];
    const float* fc2w   = (const float*)d_in[10];
    const float* fc2b   = (const float*)d_in[11];
    const float* hw1    = (const float*)d_in[12];
    const float* hb1    = (const float*)d_in[13];
    const float* hw2    = (const float*)d_in[14];
    const float* hb2    = (const float*)d_in[15];
    float* out = (float*)d_out;

    float *H, *A, *Bq, *Cv, *QT, *KT, *F;
    __nv_bfloat16 *AH, *AL, *WH, *WL;
    float *BQK, *BVO;
    cudaGetSymbolAddress((void**)&H,  g_h);
    cudaGetSymbolAddress((void**)&A,  g_a);
    cudaGetSymbolAddress((void**)&Bq, g_b);
    cudaGetSymbolAddress((void**)&Cv, g_c);
    cudaGetSymbolAddress((void**)&QT, g_qt);
    cudaGetSymbolAddress((void**)&KT, g_kt);
    cudaGetSymbolAddress((void**)&F,  g_ffn);
    cudaGetSymbolAddress((void**)&AH, g_ah);
    cudaGetSymbolAddress((void**)&AL, g_al);
    cudaGetSymbolAddress((void**)&WH, g_wh);
    cudaGetSymbolAddress((void**)&WL, g_wl);
    cudaGetSymbolAddress((void**)&BQK, g_bqk);
    cudaGetSymbolAddress((void**)&BVO, g_bvo);
    __nv_bfloat16* FH = (__nv_bfloat16*)F;
    __nv_bfloat16* FL = FH + (size_t)Mrows * FFNN;

    cudaFuncSetAttribute(gemm_bf16<0,1,0>, cudaFuncAttributeMaxDynamicSharedMemorySize, GSMEM);
    cudaFuncSetAttribute(gemm_bf16<1,0,1>, cudaFuncAttributeMaxDynamicSharedMemorySize, GSMEM);
    cudaFuncSetAttribute(gemm_qk, cudaFuncAttributeMaxDynamicSharedMemorySize, QK_SMEM);

    // launch order: posscale(0), embed(1), prep(2), gemm_qk(3)
    posscale_kernel<<<2048 + 96, 256>>>(x);
    embed_kernel<<<Bb * Tt, 128>>>(x, emb_w, emb_g, emb_b);
    prep_kernel<<<Ll * 2817, dim3(32, 8)>>>(attn_w, attn_b, fc1w, fc2w, WH, WL);

    dim3 gQ(Dd / 128, Mrows / 128);
    dim3 gQK(1024 / 128, Mrows / 128);
    dim3 gF(FFNN / 128, Mrows / 128);

    for (int l = 0; l < Ll; l++) {
        size_t lb = (size_t)l * LW;
        const float* lg0 = ln_g + (size_t)(l * 2 + 0) * Dd;
        const float* lb0 = ln_b + (size_t)(l * 2 + 0) * Dd;
        const float* lg1 = ln_g + (size_t)(l * 2 + 1) * Dd;
        const float* lb1 = ln_b + (size_t)(l * 2 + 1) * Dd;

        // merged Q,K 3-split GEMM with fused transposed (B,D,T) output
        gemm_qk<<<gQK, 256, QK_SMEM>>>(AH, AL, WH + lb + OFF_QK, WL + lb + OFF_QK,
                                       BQK + l * 1024, QT, KT);

        fft_corr_kernel<<<Bb * 64, 256>>>();
        reduce_part_kernel<<<(Bb * 1026 + 255) / 256, 256>>>();
        invtopk_kernel<<<Bb, 128>>>();

        agg_kernel<<<Bb * Tt, 128>>>(H);

        // fused (V+out)-projection: agg(H) @ Wvo + bvo + residual H -> Bq
        gemm_bf16<0,1,0><<<gQ, 256, GSMEM>>>(AH, AL, WH + lb + OFF_WVO, WL + lb + OFF_WVO,
                                             BVO + l * Dd, H, Bq, nullptr, nullptr, Mrows, Dd, Dd);
        ln_decomp_kernel<0><<<dim3(Bb, Tt / 64), 128>>>(Bq, lg0, lb0, Cv);   // h := Cv

        // FFN
        const float* f1b = fc1b + (size_t)l * FFNN;
        const float* f2b = fc2b + (size_t)l * Dd;
        gemm_bf16<1,0,1><<<gF, 256, GSMEM>>>(AH, AL, WH + lb + OFF_FC1, WL + lb + OFF_FC1,
                                             f1b, nullptr, nullptr, FH, FL, Mrows, FFNN, Dd);
        gemm_bf16<0,1,0><<<gQ, 256, GSMEM>>>(FH, FL, WH + lb + OFF_FC2, WL + lb + OFF_FC2,
                                             f2b, Cv, A, nullptr, nullptr, Mrows, Dd, FFNN);
        if (l == Ll - 1)
            ln_decomp_kernel<1><<<dim3(Bb, Tt / 64), 128>>>(A, lg1, lb1, H);  // + mean partials
        else
            ln_decomp_kernel<0><<<dim3(Bb, Tt / 64), 128>>>(A, lg1, lb1, H);
    }

    head_kernel<<<Bb, 256>>>(hw1, hb1, hw2, hb2, out);
}